// round 17
// baseline (speedup 1.0000x reference)
#include <cuda_runtime.h>
#include <cstdint>

// Problem constants (fixed by the reference setup)
#define NB 65536        // batch rows
#define NF 512          // in_features
#define NK 1299         // number of centers
#define THREADS 256
#define WPB 8                        // warps per block
#define GRID 912                     // 152 SMs * 6 blocks (40 regs -> 6 fit 64K regfile)
#define TOTAL_WARPS (GRID * WPB)     // 7296 warps; ~9 rows per warp

// Fixed-point loss accumulator: integer adds commute exactly -> bit-deterministic.
// atomicAdd return unused -> REDG (no-return), proven free in the hot kernel.
#define LOSS_SCALE 1073741824.0f     // 2^30
__device__ unsigned long long g_loss_acc;   // zero-init; finisher resets it

// Persistent single-wave kernel: each warp grid-strides over rows. Per
// iteration the chip streams one contiguous ~14.9MB input span -> sequential
// DRAM pattern preserved. No cross-block sync anywhere (0-for-6 rule):
// loss leaves via fire-and-forget REDG only.
__global__ __launch_bounds__(THREADS)
void predict_persist(const float* __restrict__ input,
                     const float* __restrict__ factor,
                     const int* __restrict__ label,     // JAX downcasts int64->int32
                     const float* __restrict__ centers,
                     float* __restrict__ pred_out)      // points at d_out+1
{
    const int warp = threadIdx.x >> 5;
    const int lane = threadIdx.x & 31;

    float lloss = 0.0f;   // meaningful in lane 0 only; per-warp fixed order

    for (int b = blockIdx.x * WPB + warp; b < NB; b += TOTAL_WARPS) {
        const float4* in4 = reinterpret_cast<const float4*>(input + (size_t)b * NF);
        int c = label[b];
        c = (c < 0) ? 0 : (c >= NK ? NK - 1 : c);       // in-bounds insurance
        const float4* ce4 = reinterpret_cast<const float4*>(centers + (size_t)c * NF);

        // input: one-pass stream -> evict-first (proven -1.8us win);
        // centers: default caching (L1 + L2-resident).
        float acc = 0.0f;
#pragma unroll
        for (int i = 0; i < 4; i++) {
            float4 a = __ldcs(&in4[lane + 32 * i]);
            float4 w = ce4[lane + 32 * i];
            acc += a.x * w.x + a.y * w.y + a.z * w.z + a.w * w.w;
        }

#pragma unroll
        for (int o = 16; o; o >>= 1)
            acc += __shfl_xor_sync(0xffffffffu, acc, o);

        if (lane == 0) {
            float p = 12.0f * tanhf(acc);
            __stcg(&pred_out[b], p);                    // streamed output, skip L1
            float d = p - factor[b];
            float ad = fabsf(d);
            lloss += (ad < 1.0f) ? 0.5f * d * d : (ad - 0.5f);
        }
    }

    // Per-warp fixed-point REDG (once per warp at its tail; no-return -> free).
    // More REDGs than per-block (7296 vs 912) but still ~0.85cyc/op at L2.
    if (lane == 0) {
        unsigned long long q = (unsigned long long)(lloss * LOSS_SCALE + 0.5f);
        atomicAdd(&g_loss_acc, q);
    }
}

// Kernel 2: trivial finisher — scale the fixed-point sum, reset accumulator.
__global__ void loss_finish_kernel(float* __restrict__ out)
{
    unsigned long long q = g_loss_acc;
    out[0] = (float)((double)q * (1.0 / ((double)LOSS_SCALE * (double)NB)));
    g_loss_acc = 0ull;                                 // clean state for next replay
}

extern "C" void kernel_launch(void* const* d_in, const int* in_sizes, int n_in,
                              void* d_out, int out_size)
{
    // metadata order follows setup_inputs: input, factor, label, centers
    const float* input   = (const float*)d_in[0];
    const float* factor  = (const float*)d_in[1];
    const int*   label   = (const int*)d_in[2];
    const float* centers = (const float*)d_in[3];

    float* out = (float*)d_out;   // out[0]=loss, out[1..NB]=predict_a
    float* pred_out = out + 1;

    predict_persist<<<GRID, THREADS>>>(input, factor, label, centers, pred_out);
    loss_finish_kernel<<<1, 1>>>(out);
}